// round 15
// baseline (speedup 1.0000x reference)
#include <cuda_runtime.h>
#include <math.h>
#include <stdint.h>

// Problem dims
constexpr int NB = 128;    // batch
constexpr int NL = 1024;   // seq len
constexpr int NE = 64;     // embed
constexpr int NH = 512;    // hidden
constexpr int NV = 96;     // vocab

// RNN kernel config (L2 mailboxes + fence/flag protocol)
constexpr int CS   = 8;          // CTAs per group
constexpr int RPC  = 8;          // batch rows per group
constexpr int NCL  = NB / RPC;   // 16 groups
constexpr int GRNN = NCL * CS;   // 128 CTAs
constexpr int TRNN = 512;        // threads per CTA (one per output col)
constexpr int KS   = NH / CS;    // 64 k-values owned per CTA

// SMEM: prologue scratch (NV*NE + NE*KS = 10240 f) overlays steady state
// (sproj 6144 + sh 512 + tok).
constexpr int SM_PROJ = NV * KS;
constexpr int SM_HH   = RPC * KS;
constexpr int RNN_SMEM_BYTES = (NV * NE + NE * KS) * 4 + 256; // 41KB

// Logits kernel config (persistent, 8 rows/warp)
constexpr int LG_GRID = 148;
constexpr int LG_TILE = 128;
constexpr int LG_NTILES = NB * NL / LG_TILE;
constexpr int SMEM_LOG_BYTES = (NH / 2) * NV * 8; // 196608 B

// Scratch (device globals: allocation-free rule).
// g_flag MUST be 16B-aligned: the consumer polls it with 16B vector loads
// (R13/R14 failed because a 4B-aligned base made those loads illegal).
__device__ float g_hs[(size_t)NB * NL * NH];          // 256 MB: all h_t
__device__ float g_part[2 * NCL * CS * RPC * NH];     // 2 MB partial mailboxes
__device__ __align__(16) int g_flag[2 * NCL * CS];    // 256 flags (zero-init)

// ---------------------------------------------------------------------------
// Helpers
// ---------------------------------------------------------------------------
__device__ __forceinline__ unsigned long long packf2(float lo, float hi) {
    return (unsigned long long)__float_as_uint(lo) |
           ((unsigned long long)__float_as_uint(hi) << 32);
}
__device__ __forceinline__ float f2lo(unsigned long long v) {
    return __uint_as_float((uint32_t)v);
}
__device__ __forceinline__ float f2hi(unsigned long long v) {
    return __uint_as_float((uint32_t)(v >> 32));
}
#define FMA2(acc, a, b) \
    asm volatile("fma.rn.f32x2 %0, %1, %2, %0;" : "+l"(acc) : "l"(a), "l"(b))

__device__ __forceinline__ int ld_acq(const int* p) {
    int v;
    asm volatile("ld.acquire.gpu.global.s32 %0, [%1];" : "=r"(v) : "l"(p) : "memory");
    return v;
}
__device__ __forceinline__ int4 ldcg_v4(const int4* p) {
    int4 v;
    asm volatile("ld.global.cg.v4.u32 {%0,%1,%2,%3}, [%4];"
                 : "=r"(v.x), "=r"(v.y), "=r"(v.z), "=r"(v.w) : "l"(p) : "memory");
    return v;
}

// Flag reset for the NEXT call (graph replays reuse the flag array).
__global__ void clear_flags_kernel() { g_flag[threadIdx.x] = 0; }

// ---------------------------------------------------------------------------
// Kernel 1: recurrence with fused input projection.
// Producer protocol = R11 EXACT (proven correct): store partials ->
// __syncthreads -> tid0 fence.acq_rel.gpu (MEMBAR drains the WHOLE SM's
// outstanding global stores) + st.relaxed flag = t+1.
// Consumer: ALL threads poll the 8 group flags via two (now-aligned) 16B cg
// loads, then per-flag CHECKED acquire loads (each thread independently
// synchronizes with every producer's fence) -> no tid<8 spin, no broadcast
// __syncthreads (3 -> 2 barriers per step).
// ---------------------------------------------------------------------------
__global__ __launch_bounds__(TRNN, 1)
void rnn11_kernel(const void* __restrict__ xraw,
                  const float* __restrict__ h0,
                  const float* __restrict__ Whh,
                  const float* __restrict__ emb,
                  const float* __restrict__ Wxh,
                  const float* __restrict__ bh,
                  float* __restrict__ finalh) {
    extern __shared__ float sm[];
    float* sproj = sm;                       // [NV][KS]
    float* sh    = sm + SM_PROJ;             // [RPC][KS]
    int*   stok  = (int*)(sh + SM_HH);       // [2][RPC]

    const int tid     = threadIdx.x;
    const int rank    = blockIdx.x & (CS - 1);
    const int cl      = blockIdx.x >> 3;
    const int row0    = cl * RPC;
    const int colbase = rank * KS;
    const int j       = tid;            // global output column 0..511
    const int rr      = tid >> 6;       // reduce-phase row
    const int rjl     = tid & (KS - 1); // reduce-phase col-in-slice

    // Detect x dtype: int64 (odd int32 words all zero) vs int32.
    const int* xi = (const int*)xraw;
    bool is64 = true;
    for (int i = 1; i < 128; i += 2) {
        if (xi[i] != 0) { is64 = false; break; }
    }
    const long long* x64 = (const long long*)xraw;
    const int*       x32 = (const int*)xraw;

    // ---- fused proj: sproj[v][c] = bh[cb+c] + sum_e emb[v][e]*Wxh[e][cb+c]
    {
        float* semb = sm;            // [NV][NE]  6144 f (scratch)
        float* swx  = sm + NV * NE;  // [NE][KS]  4096 f (scratch)
        for (int i = tid; i < NV * NE; i += TRNN) semb[i] = emb[i];
        for (int i = tid; i < NE * KS; i += TRNN) {
            int e = i >> 6, c = i & (KS - 1);
            swx[i] = Wxh[e * NH + colbase + c];
        }
        __syncthreads();
        float pr[NV * KS / TRNN];   // 12 outputs per thread
        #pragma unroll
        for (int o = 0; o < NV * KS / TRNN; o++) {
            int idx = o * TRNN + tid;
            int v = idx >> 6, c = idx & (KS - 1);
            float acc = bh[colbase + c];
            #pragma unroll 8
            for (int e = 0; e < NE; e++) acc += semb[v * NE + e] * swx[e * KS + c];
            pr[o] = acc;
        }
        __syncthreads();
        #pragma unroll
        for (int o = 0; o < NV * KS / TRNN; o++) sproj[o * TRNN + tid] = pr[o];
    }

    // W_hh slice -> registers, packed (W[cb+2p][j], W[cb+2p+1][j])
    unsigned long long wreg[KS / 2];
    {
        const float* Wb = Whh + (size_t)colbase * NH + j;
        #pragma unroll
        for (int p = 0; p < KS / 2; p++) {
            wreg[p] = packf2(Wb[(size_t)(2 * p) * NH], Wb[(size_t)(2 * p + 1) * NH]);
        }
    }
    // h init; tokens t=0
    sh[tid] = h0[(size_t)(row0 + rr) * NH + colbase + rjl];
    if (tid < RPC) {
        size_t idx = (size_t)(row0 + tid) * NL;
        stok[tid] = is64 ? (int)x64[idx] : x32[idx];
    }
    __syncthreads();

    // Mailbox pointers. Layout: g_part[pb][cl][src][r][col(NH)]
    constexpr int PB_OFF = NCL * CS * RPC * NH;
    float* pbase = g_part + ((size_t)(cl * CS + rank) * RPC) * NH + j;  // producer
    const float* cbase = g_part + ((size_t)(cl * CS) * RPC + rr) * NH + colbase + rjl;

    float* gdst = g_hs + (size_t)(row0 + rr) * NL * NH + colbase + rjl;
    float hprev = 0.f;

    for (int t = 0; t < NL; t++) {
        const int pb = t & 1;
        float* pdst = pbase + pb * PB_OFF;
        int* fgrp = g_flag + pb * NCL * CS + cl * CS;   // 32B-offset, 16B-aligned

        // ---- compute + immediate coalesced STG, one batch row at a time ----
        #pragma unroll 2
        for (int r = 0; r < RPC; r++) {
            unsigned long long a0 = 0ull, a1 = 0ull;
            #pragma unroll
            for (int p2 = 0; p2 < KS / 4; p2++) {
                ulonglong2 hh = *(const ulonglong2*)&sh[r * KS + p2 * 4];
                FMA2(a0, wreg[2 * p2],     hh.x);
                FMA2(a1, wreg[2 * p2 + 1], hh.y);
            }
            float v = (f2lo(a0) + f2hi(a0)) + (f2lo(a1) + f2hi(a1));
            __stcg(pdst + r * NH, v);
        }

        __syncthreads();   // all threads' partial stores issued

        // release: MEMBAR.GPU drains ALL threads' stores, then post flag
        if (tid == 0) {
            asm volatile("fence.acq_rel.gpu;" ::: "memory");
            asm volatile("st.relaxed.gpu.global.s32 [%0], %1;"
                         :: "l"(fgrp + rank), "r"(t + 1) : "memory");
        }

        // deferred work while partials fly: previous h -> gmem, next token
        if (t > 0) gdst[(size_t)(t - 1) * NH] = hprev;
        int tok_next = 0;
        if (tid < RPC && t + 1 < NL) {
            size_t idx = (size_t)(row0 + tid) * NL + (t + 1);
            tok_next = is64 ? (int)x64[idx] : x32[idx];
        }

        // all-thread poll: two 16B cg loads over the 8 flags, then CHECKED
        // acquire loads (establish sync-with per producer, per thread)
        {
            const int4* f4 = (const int4*)fgrp;
            for (;;) {
                int4 a = ldcg_v4(f4);
                int4 b = ldcg_v4(f4 + 1);
                if (a.x >= t + 1 && a.y >= t + 1 && a.z >= t + 1 && a.w >= t + 1 &&
                    b.x >= t + 1 && b.y >= t + 1 && b.z >= t + 1 && b.w >= t + 1)
                    break;
            }
            #pragma unroll
            for (int s = 0; s < CS; s++) {
                while (ld_acq(fgrp + s) < t + 1) { }
            }
        }

        // ---- reduce own column: 8 partials (L2) + proj + tanh ----
        {
            const float* c0 = cbase + pb * PB_OFF;
            float s = 0.f;
            #pragma unroll
            for (int s8 = 0; s8 < CS; s8++)
                s += __ldcg(c0 + (size_t)s8 * RPC * NH);
            s += sproj[stok[pb * RPC + rr] * KS + rjl];
            hprev = tanhf(s);
            sh[rr * KS + rjl] = hprev;
        }
        if (tid < RPC) stok[((t + 1) & 1) * RPC + tid] = tok_next;
        __syncthreads();
    }

    gdst[(size_t)(NL - 1) * NH] = hprev;
    if (finalh) finalh[(row0 + rr) * NH + colbase + rjl] = hprev;
}

// ---------------------------------------------------------------------------
// Kernel 2: persistent logits GEMM (unchanged: measured 352us).
// ---------------------------------------------------------------------------
__global__ __launch_bounds__(512, 1)
void logits3_kernel(const float* __restrict__ fcw,
                    const float* __restrict__ fcb,
                    float* __restrict__ out) {
    extern __shared__ unsigned long long spk[];  // [NH/2][NV] packed pairs
    const int tid  = threadIdx.x;
    const int lane = tid & 31;
    const int warp = tid >> 5;

    for (int i = tid; i < (NH / 2) * NV; i += 512) {
        int k2 = i / NV, c = i - k2 * NV;
        spk[i] = packf2(fcw[(2 * k2) * NV + c], fcw[(2 * k2 + 1) * NV + c]);
    }
    float b[3];
    #pragma unroll
    for (int g = 0; g < 3; g++) b[g] = fcb[g * 32 + lane];
    __syncthreads();

    for (int tile = blockIdx.x; tile < LG_NTILES; tile += gridDim.x) {
        const size_t row0 = (size_t)tile * LG_TILE + warp * 8;
        const float* hsr = g_hs + row0 * NH;

        unsigned long long acc[8][3];
        #pragma unroll
        for (int i = 0; i < 8; i++)
            #pragma unroll
            for (int g = 0; g < 3; g++) acc[i][g] = 0ull;

        for (int k4 = 0; k4 < NH / 4; k4++) {
            ulonglong2 hp[8];
            #pragma unroll
            for (int i = 0; i < 8; i++)
                hp[i] = *(const ulonglong2*)&hsr[(size_t)i * NH + 4 * k4];
            #pragma unroll
            for (int g = 0; g < 3; g++) {
                unsigned long long w0 = spk[(2 * k4) * NV + g * 32 + lane];
                unsigned long long w1 = spk[(2 * k4 + 1) * NV + g * 32 + lane];
                #pragma unroll
                for (int i = 0; i < 8; i++) {
                    FMA2(acc[i][g], hp[i].x, w0);
                    FMA2(acc[i][g], hp[i].y, w1);
                }
            }
        }
        #pragma unroll
        for (int i = 0; i < 8; i++)
            #pragma unroll
            for (int g = 0; g < 3; g++) {
                float s = f2lo(acc[i][g]) + f2hi(acc[i][g]) + b[g];
                out[(row0 + i) * NV + g * 32 + lane] = s;
            }
    }
}

// ---------------------------------------------------------------------------
// Launch
// ---------------------------------------------------------------------------
extern "C" void kernel_launch(void* const* d_in, const int* in_sizes, int n_in,
                              void* d_out, int out_size) {
    const void*  x      = d_in[0];                 // [B,L] int64 or int32
    const float* hidden = (const float*)d_in[1];   // [B,H]
    const float* emb    = (const float*)d_in[2];   // [V,E]
    const float* Wxh    = (const float*)d_in[3];   // [E,H]
    const float* Whh    = (const float*)d_in[4];   // [H,H]
    const float* bh     = (const float*)d_in[5];   // [H]
    const float* fcw    = (const float*)d_in[6];   // [H,V]
    const float* fcb    = (const float*)d_in[7];   // [V]

    float* out = (float*)d_out;                    // logits [B,L,V] ...
    const size_t logitsN = (size_t)NB * NL * NV;
    float* finalh = (out_size >= (int)(logitsN + (size_t)NB * NH))
                        ? out + logitsN : nullptr; // ... then final_h [B,H]

    cudaFuncSetAttribute(rnn11_kernel,
                         cudaFuncAttributeMaxDynamicSharedMemorySize,
                         RNN_SMEM_BYTES);
    cudaFuncSetAttribute(logits3_kernel,
                         cudaFuncAttributeMaxDynamicSharedMemorySize,
                         SMEM_LOG_BYTES);

    rnn11_kernel<<<GRNN, TRNN, RNN_SMEM_BYTES>>>(x, hidden, Whh, emb, Wxh, bh, finalh);
    logits3_kernel<<<LG_GRID, 512, SMEM_LOG_BYTES>>>(fcw, fcb, out);
    clear_flags_kernel<<<1, 2 * NCL * CS>>>();
}

// round 16
// speedup vs baseline: 3.1731x; 3.1731x over previous
#include <cuda_runtime.h>
#include <math.h>
#include <stdint.h>

// Problem dims
constexpr int NB = 128;    // batch
constexpr int NL = 1024;   // seq len
constexpr int NE = 64;     // embed
constexpr int NH = 512;    // hidden
constexpr int NV = 96;     // vocab

// RNN kernel config (L2 mailboxes + fence/flag protocol, half-step pipeline)
constexpr int CS   = 8;          // CTAs per group
constexpr int RPC  = 8;          // batch rows per group
constexpr int HR   = RPC / 2;    // rows per half-step (4)
constexpr int NCL  = NB / RPC;   // 16 groups
constexpr int GRNN = NCL * CS;   // 128 CTAs
constexpr int TRNN = 512;        // threads per CTA (one per output col)
constexpr int KS   = NH / CS;    // 64 k-values owned per CTA

// SMEM: prologue scratch (NV*NE + NE*KS = 10240 f) overlays steady state
// (sproj 6144 + sh 512 + tok).
constexpr int SM_PROJ = NV * KS;
constexpr int SM_HH   = RPC * KS;
constexpr int RNN_SMEM_BYTES = (NV * NE + NE * KS) * 4 + 256; // 41KB

// Logits kernel config (persistent, 8 rows/warp)
constexpr int LG_GRID = 148;
constexpr int LG_TILE = 128;
constexpr int LG_NTILES = NB * NL / LG_TILE;
constexpr int SMEM_LOG_BYTES = (NH / 2) * NV * 8; // 196608 B

// Scratch (device globals: allocation-free rule)
__device__ float g_hs[(size_t)NB * NL * NH];          // 256 MB: all h_t
__device__ float g_part[2 * NCL * CS * RPC * NH];     // 2 MB partial mailboxes
__device__ int   g_flag[2 * 2 * NCL * CS];            // [half][pb][cl][src] (zero-init)

// ---------------------------------------------------------------------------
// Helpers
// ---------------------------------------------------------------------------
__device__ __forceinline__ unsigned long long packf2(float lo, float hi) {
    return (unsigned long long)__float_as_uint(lo) |
           ((unsigned long long)__float_as_uint(hi) << 32);
}
__device__ __forceinline__ float f2lo(unsigned long long v) {
    return __uint_as_float((uint32_t)v);
}
__device__ __forceinline__ float f2hi(unsigned long long v) {
    return __uint_as_float((uint32_t)(v >> 32));
}
#define FMA2(acc, a, b) \
    asm volatile("fma.rn.f32x2 %0, %1, %2, %0;" : "+l"(acc) : "l"(a), "l"(b))

__device__ __forceinline__ int ld_acq(const int* p) {
    int v;
    asm volatile("ld.acquire.gpu.global.s32 %0, [%1];" : "=r"(v) : "l"(p) : "memory");
    return v;
}

// Flag reset for the NEXT call (graph replays reuse the flag array).
__global__ void clear_flags_kernel() { g_flag[threadIdx.x] = 0; }

// ---------------------------------------------------------------------------
// Kernel 1: recurrence, half-step pipelined (single delta vs R11 best):
//   computeA(rows 0-3) -> sync -> fence+flagA
//   computeB(rows 4-7) -> sync -> fence+flagB   (overlaps A's flight)
//   deferred g_hs store + token prefetch
//   spinA(tid<8, acquire) -> sync -> reduceA (threads rr<4)
//   spinB(tid<8, acquire) -> sync -> reduceB (threads rr>=4) -> sync
// All primitives are R11-exact (proven correct); monotonic flags + pb
// double-buffering give the same t->t+2 backpressure proof per half.
// ---------------------------------------------------------------------------
__global__ __launch_bounds__(TRNN, 1)
void rnn12_kernel(const void* __restrict__ xraw,
                  const float* __restrict__ h0,
                  const float* __restrict__ Whh,
                  const float* __restrict__ emb,
                  const float* __restrict__ Wxh,
                  const float* __restrict__ bh,
                  float* __restrict__ finalh) {
    extern __shared__ float sm[];
    float* sproj = sm;                       // [NV][KS]
    float* sh    = sm + SM_PROJ;             // [RPC][KS]
    int*   stok  = (int*)(sh + SM_HH);       // [2][RPC]

    const int tid     = threadIdx.x;
    const int rank    = blockIdx.x & (CS - 1);
    const int cl      = blockIdx.x >> 3;
    const int row0    = cl * RPC;
    const int colbase = rank * KS;
    const int j       = tid;            // global output column 0..511
    const int rr      = tid >> 6;       // reduce-phase row
    const int rjl     = tid & (KS - 1); // reduce-phase col-in-slice
    const int myhalf  = rr >> 2;        // 0: reduce in phase A, 1: phase B

    // Detect x dtype: int64 (odd int32 words all zero) vs int32.
    const int* xi = (const int*)xraw;
    bool is64 = true;
    for (int i = 1; i < 128; i += 2) {
        if (xi[i] != 0) { is64 = false; break; }
    }
    const long long* x64 = (const long long*)xraw;
    const int*       x32 = (const int*)xraw;

    // ---- fused proj: sproj[v][c] = bh[cb+c] + sum_e emb[v][e]*Wxh[e][cb+c]
    {
        float* semb = sm;            // [NV][NE]  6144 f (scratch)
        float* swx  = sm + NV * NE;  // [NE][KS]  4096 f (scratch)
        for (int i = tid; i < NV * NE; i += TRNN) semb[i] = emb[i];
        for (int i = tid; i < NE * KS; i += TRNN) {
            int e = i >> 6, c = i & (KS - 1);
            swx[i] = Wxh[e * NH + colbase + c];
        }
        __syncthreads();
        float pr[NV * KS / TRNN];   // 12 outputs per thread
        #pragma unroll
        for (int o = 0; o < NV * KS / TRNN; o++) {
            int idx = o * TRNN + tid;
            int v = idx >> 6, c = idx & (KS - 1);
            float acc = bh[colbase + c];
            #pragma unroll 8
            for (int e = 0; e < NE; e++) acc += semb[v * NE + e] * swx[e * KS + c];
            pr[o] = acc;
        }
        __syncthreads();
        #pragma unroll
        for (int o = 0; o < NV * KS / TRNN; o++) sproj[o * TRNN + tid] = pr[o];
    }

    // W_hh slice -> registers, packed (W[cb+2p][j], W[cb+2p+1][j])
    unsigned long long wreg[KS / 2];
    {
        const float* Wb = Whh + (size_t)colbase * NH + j;
        #pragma unroll
        for (int p = 0; p < KS / 2; p++) {
            wreg[p] = packf2(Wb[(size_t)(2 * p) * NH], Wb[(size_t)(2 * p + 1) * NH]);
        }
    }
    // h init; tokens t=0
    sh[tid] = h0[(size_t)(row0 + rr) * NH + colbase + rjl];
    if (tid < RPC) {
        size_t idx = (size_t)(row0 + tid) * NL;
        stok[tid] = is64 ? (int)x64[idx] : x32[idx];
    }
    __syncthreads();

    // Mailbox pointers. Layout: g_part[pb][cl][src][r][col(NH)]
    constexpr int PB_OFF = NCL * CS * RPC * NH;
    constexpr int HALF_OFF = 2 * NCL * CS;     // flag stride between halves
    float* pbase = g_part + ((size_t)(cl * CS + rank) * RPC) * NH + j;  // producer
    const float* cbase = g_part + ((size_t)(cl * CS) * RPC + rr) * NH + colbase + rjl;

    float* gdst = g_hs + (size_t)(row0 + rr) * NL * NH + colbase + rjl;
    float hprev = 0.f;

    for (int t = 0; t < NL; t++) {
        const int pb = t & 1;
        float* pdst = pbase + pb * PB_OFF;
        int* fgA = g_flag + pb * NCL * CS + cl * CS;              // half A flags
        int* fgB = fgA + HALF_OFF;                                // half B flags

        // ---- half A: compute rows 0..3 + STG ----
        #pragma unroll 2
        for (int r = 0; r < HR; r++) {
            unsigned long long a0 = 0ull, a1 = 0ull;
            #pragma unroll
            for (int p2 = 0; p2 < KS / 4; p2++) {
                ulonglong2 hh = *(const ulonglong2*)&sh[r * KS + p2 * 4];
                FMA2(a0, wreg[2 * p2],     hh.x);
                FMA2(a1, wreg[2 * p2 + 1], hh.y);
            }
            float v = (f2lo(a0) + f2hi(a0)) + (f2lo(a1) + f2hi(a1));
            __stcg(pdst + r * NH, v);
        }
        __syncthreads();
        if (tid == 0) {
            asm volatile("fence.acq_rel.gpu;" ::: "memory");
            asm volatile("st.relaxed.gpu.global.s32 [%0], %1;"
                         :: "l"(fgA + rank), "r"(t + 1) : "memory");
        }

        // ---- half B: compute rows 4..7 + STG (overlaps A's flight) ----
        #pragma unroll 2
        for (int r = HR; r < RPC; r++) {
            unsigned long long a0 = 0ull, a1 = 0ull;
            #pragma unroll
            for (int p2 = 0; p2 < KS / 4; p2++) {
                ulonglong2 hh = *(const ulonglong2*)&sh[r * KS + p2 * 4];
                FMA2(a0, wreg[2 * p2],     hh.x);
                FMA2(a1, wreg[2 * p2 + 1], hh.y);
            }
            float v = (f2lo(a0) + f2hi(a0)) + (f2lo(a1) + f2hi(a1));
            __stcg(pdst + r * NH, v);
        }
        __syncthreads();
        if (tid == 0) {
            asm volatile("fence.acq_rel.gpu;" ::: "memory");
            asm volatile("st.relaxed.gpu.global.s32 [%0], %1;"
                         :: "l"(fgB + rank), "r"(t + 1) : "memory");
        }

        // deferred work while partials fly: previous h -> gmem, next token
        if (t > 0) gdst[(size_t)(t - 1) * NH] = hprev;
        int tok_next = 0;
        if (tid < RPC && t + 1 < NL) {
            size_t idx = (size_t)(row0 + tid) * NL + (t + 1);
            tok_next = is64 ? (int)x64[idx] : x32[idx];
        }

        // ---- consume half A ----
        if (tid < CS) {
            while (ld_acq(fgA + tid) < t + 1) { }
        }
        __syncthreads();
        if (myhalf == 0) {
            const float* c0 = cbase + pb * PB_OFF;
            float s = 0.f;
            #pragma unroll
            for (int s8 = 0; s8 < CS; s8++)
                s += __ldcg(c0 + (size_t)s8 * RPC * NH);
            s += sproj[stok[pb * RPC + rr] * KS + rjl];
            hprev = tanhf(s);
            sh[rr * KS + rjl] = hprev;
        }

        // ---- consume half B ----
        if (tid < CS) {
            while (ld_acq(fgB + tid) < t + 1) { }
        }
        __syncthreads();
        if (myhalf == 1) {
            const float* c0 = cbase + pb * PB_OFF;
            float s = 0.f;
            #pragma unroll
            for (int s8 = 0; s8 < CS; s8++)
                s += __ldcg(c0 + (size_t)s8 * RPC * NH);
            s += sproj[stok[pb * RPC + rr] * KS + rjl];
            hprev = tanhf(s);
            sh[rr * KS + rjl] = hprev;
        }
        if (tid < RPC) stok[((t + 1) & 1) * RPC + tid] = tok_next;
        __syncthreads();
    }

    gdst[(size_t)(NL - 1) * NH] = hprev;
    if (finalh) finalh[(row0 + rr) * NH + colbase + rjl] = hprev;
}

// ---------------------------------------------------------------------------
// Kernel 2: persistent logits GEMM (unchanged: measured 352us).
// ---------------------------------------------------------------------------
__global__ __launch_bounds__(512, 1)
void logits3_kernel(const float* __restrict__ fcw,
                    const float* __restrict__ fcb,
                    float* __restrict__ out) {
    extern __shared__ unsigned long long spk[];  // [NH/2][NV] packed pairs
    const int tid  = threadIdx.x;
    const int lane = tid & 31;
    const int warp = tid >> 5;

    for (int i = tid; i < (NH / 2) * NV; i += 512) {
        int k2 = i / NV, c = i - k2 * NV;
        spk[i] = packf2(fcw[(2 * k2) * NV + c], fcw[(2 * k2 + 1) * NV + c]);
    }
    float b[3];
    #pragma unroll
    for (int g = 0; g < 3; g++) b[g] = fcb[g * 32 + lane];
    __syncthreads();

    for (int tile = blockIdx.x; tile < LG_NTILES; tile += gridDim.x) {
        const size_t row0 = (size_t)tile * LG_TILE + warp * 8;
        const float* hsr = g_hs + row0 * NH;

        unsigned long long acc[8][3];
        #pragma unroll
        for (int i = 0; i < 8; i++)
            #pragma unroll
            for (int g = 0; g < 3; g++) acc[i][g] = 0ull;

        for (int k4 = 0; k4 < NH / 4; k4++) {
            ulonglong2 hp[8];
            #pragma unroll
            for (int i = 0; i < 8; i++)
                hp[i] = *(const ulonglong2*)&hsr[(size_t)i * NH + 4 * k4];
            #pragma unroll
            for (int g = 0; g < 3; g++) {
                unsigned long long w0 = spk[(2 * k4) * NV + g * 32 + lane];
                unsigned long long w1 = spk[(2 * k4 + 1) * NV + g * 32 + lane];
                #pragma unroll
                for (int i = 0; i < 8; i++) {
                    FMA2(acc[i][g], hp[i].x, w0);
                    FMA2(acc[i][g], hp[i].y, w1);
                }
            }
        }
        #pragma unroll
        for (int i = 0; i < 8; i++)
            #pragma unroll
            for (int g = 0; g < 3; g++) {
                float s = f2lo(acc[i][g]) + f2hi(acc[i][g]) + b[g];
                out[(row0 + i) * NV + g * 32 + lane] = s;
            }
    }
}

// ---------------------------------------------------------------------------
// Launch
// ---------------------------------------------------------------------------
extern "C" void kernel_launch(void* const* d_in, const int* in_sizes, int n_in,
                              void* d_out, int out_size) {
    const void*  x      = d_in[0];                 // [B,L] int64 or int32
    const float* hidden = (const float*)d_in[1];   // [B,H]
    const float* emb    = (const float*)d_in[2];   // [V,E]
    const float* Wxh    = (const float*)d_in[3];   // [E,H]
    const float* Whh    = (const float*)d_in[4];   // [H,H]
    const float* bh     = (const float*)d_in[5];   // [H]
    const float* fcw    = (const float*)d_in[6];   // [H,V]
    const float* fcb    = (const float*)d_in[7];   // [V]

    float* out = (float*)d_out;                    // logits [B,L,V] ...
    const size_t logitsN = (size_t)NB * NL * NV;
    float* finalh = (out_size >= (int)(logitsN + (size_t)NB * NH))
                        ? out + logitsN : nullptr; // ... then final_h [B,H]

    cudaFuncSetAttribute(rnn12_kernel,
                         cudaFuncAttributeMaxDynamicSharedMemorySize,
                         RNN_SMEM_BYTES);
    cudaFuncSetAttribute(logits3_kernel,
                         cudaFuncAttributeMaxDynamicSharedMemorySize,
                         SMEM_LOG_BYTES);

    rnn12_kernel<<<GRNN, TRNN, RNN_SMEM_BYTES>>>(x, hidden, Whh, emb, Wxh, bh, finalh);
    logits3_kernel<<<LG_GRID, 512, SMEM_LOG_BYTES>>>(fcw, fcb, out);
    clear_flags_kernel<<<1, 2 * 2 * NCL * CS>>>();
}